// round 2
// baseline (speedup 1.0000x reference)
#include <cuda_runtime.h>

#define NCLS 19
#define HW   (512 * 512)
#define NPIX (8 * HW)
#define BLOCK 256
#define NBLK (NPIX / BLOCK)   // 8192

__device__ double g_partial[NBLK];
__device__ int    g_count[NBLK];

__device__ __forceinline__ float warp_sum_f(float v) {
#pragma unroll
    for (int o = 16; o; o >>= 1) v += __shfl_down_sync(0xffffffffu, v, o);
    return v;
}
__device__ __forceinline__ int warp_sum_i(int v) {
#pragma unroll
    for (int o = 16; o; o >>= 1) v += __shfl_down_sync(0xffffffffu, v, o);
    return v;
}

__global__ void __launch_bounds__(BLOCK) lms_main_kernel(
    const float* __restrict__ logits, const int* __restrict__ labels)
{
    const int pix = blockIdx.x * BLOCK + threadIdx.x;   // grid covers NPIX exactly
    const int n  = pix / HW;
    const int hw = pix - n * HW;
    const float* base = logits + (size_t)n * NCLS * HW + hw;

    // Batch all 19 class loads up front: coalesced, MLP=19.
    float x[NCLS];
#pragma unroll
    for (int c = 0; c < NCLS; c++) x[c] = __ldg(base + (size_t)c * HW);

    const int lb = labels[pix];

    float loss = 0.0f;
    int valid = 0;
    if (lb >= 0 && lb < NCLS) {
        valid = 1;
        float mx = x[0];
#pragma unroll
        for (int c = 1; c < NCLS; c++) mx = fmaxf(mx, x[c]);

        float se = 0.0f, sx = 0.0f, dot = 0.0f, xl = 0.0f, el = 0.0f;
#pragma unroll
        for (int c = 0; c < NCLS; c++) {
            const float e = __expf(x[c] - mx);
            se  += e;
            sx  += x[c];
            dot  = fmaf(e, x[c], dot);
            if (c == lb) { xl = x[c]; el = e; }   // predicated select, no spill
        }
        const float se2  = se - el;               // softmax denom over non-label classes
        const float lse  = mx + __logf(se);
        const float ce   = lse - xl;              // cross-entropy term
        const float dot2 = dot - el * xl;         // Σ_{c≠lb} e_c x_c
        // margin = lam * (Σ q_c x_c − coeff Σ x_c), q_c = e_c/se2 ; lse2 cancels.
        const float margin = 0.15f * (dot2 / se2 - (1.0f / 18.0f) * (sx - xl));
        loss = ce + margin;
    }

    // Deterministic block reduction: warp shuffle then smem across 8 warps.
    float v = warp_sum_f(loss);
    int   c = warp_sum_i(valid);

    __shared__ float sv[BLOCK / 32];
    __shared__ int   sc[BLOCK / 32];
    const int lane = threadIdx.x & 31;
    const int wid  = threadIdx.x >> 5;
    if (lane == 0) { sv[wid] = v; sc[wid] = c; }
    __syncthreads();
    if (wid == 0) {
        float bv = (lane < BLOCK / 32) ? sv[lane] : 0.0f;
        int   bc = (lane < BLOCK / 32) ? sc[lane] : 0;
        bv = warp_sum_f(bv);
        bc = warp_sum_i(bc);
        if (lane == 0) {
            g_partial[blockIdx.x] = (double)bv;   // overwrite each replay: graph-safe
            g_count[blockIdx.x]   = bc;
        }
    }
}

__global__ void __launch_bounds__(1024) lms_reduce_kernel(float* __restrict__ out)
{
    double s = 0.0;
    long long cnt = 0;
    for (int i = threadIdx.x; i < NBLK; i += 1024) {
        s   += g_partial[i];
        cnt += g_count[i];
    }
#pragma unroll
    for (int o = 16; o; o >>= 1) {
        s   += __shfl_down_sync(0xffffffffu, s, o);
        cnt += __shfl_down_sync(0xffffffffu, cnt, o);
    }
    __shared__ double    ss[32];
    __shared__ long long sn[32];
    const int lane = threadIdx.x & 31;
    const int wid  = threadIdx.x >> 5;
    if (lane == 0) { ss[wid] = s; sn[wid] = cnt; }
    __syncthreads();
    if (wid == 0) {
        double    bs = (lane < 32) ? ss[lane] : 0.0;
        long long bn = (lane < 32) ? sn[lane] : 0;
#pragma unroll
        for (int o = 16; o; o >>= 1) {
            bs += __shfl_down_sync(0xffffffffu, bs, o);
            bn += __shfl_down_sync(0xffffffffu, bn, o);
        }
        if (lane == 0) out[0] = (float)(bs / (double)bn);
    }
}

extern "C" void kernel_launch(void* const* d_in, const int* in_sizes, int n_in,
                              void* d_out, int out_size)
{
    const float* logits = (const float*)d_in[0];
    const int*   labels = (const int*)d_in[1];
    float*       out    = (float*)d_out;

    lms_main_kernel<<<NBLK, BLOCK>>>(logits, labels);
    lms_reduce_kernel<<<1, 1024>>>(out);
}